// round 17
// baseline (speedup 1.0000x reference)
#include <cuda_runtime.h>

// Problem constants
#define D_H      512
#define D_MODEL  2048
#define BB       4
#define TT       4096
#define O4       (D_MODEL / 4)     // 512 float4 columns per row

#define GA       256               // kernel A (GEMV) blocks — R7-proven population
#define GB       592               // kernel B (stream) blocks: 4 x 148
#define NT       256

#define NKM      32
#define KCM      (D_H / NKM)       // 16 rows per k-chunk (phase 1)
#define NKV      32
#define KCV      (D_MODEL / NKV)   // 64 rows per k-chunk (phases 2,3)

// Stream: static balanced split of 16384 rows over 592 blocks
#define NROWS    (BB * TT)                         // 16384
#define RPB_LO   (NROWS / GB)                      // 27
#define RPB_REM  (NROWS - RPB_LO * GB)             // 400 blocks get 28
#define PF_LINES 3                                 // 3 x 256 lines = 12 rows prefetched/block

// Scratch (__device__ globals; no allocation allowed)
__device__ __align__(16) float g_PM [NKM * BB * D_MODEL];   // 1 MB
__device__ __align__(16) float g_PV [NKV * BB * D_MODEL];   // 1 MB
__device__ __align__(16) float g_POV[NKV * BB * D_MODEL];   // 1 MB
__device__ __align__(16) float g_OV [BB * D_MODEL];         // 32 KB
__device__ __align__(128) unsigned g_bar;                   // monotonic barrier counter

// GEMV-internal grid barrier (population GA, 3 uses/launch; graph-replay safe).
__device__ __forceinline__ void gemv_bar(unsigned base, unsigned phase) {
    __syncthreads();
    if (threadIdx.x == 0) {
        __threadfence();
        atomicAdd(&g_bar, 1u);
        const unsigned tgt = base + phase * GA;
        while (atomicAdd(&g_bar, 0u) < tgt) __nanosleep(64);
        __threadfence();
    }
    __syncthreads();
}

// ---------------------------------------------------------------------------
// Kernel A: GEMV chain (R7's proven phases).  Signals PDL dependents at entry.
// ---------------------------------------------------------------------------
__global__ void __launch_bounds__(NT) k_gemv(
    const float* __restrict__ zH,  const float* __restrict__ Wm,
    const float* __restrict__ Wv,  const float* __restrict__ Wo,
    const float* __restrict__ gate)
{
    // Allow the dependent stream kernel to begin launching immediately.
    asm volatile("griddepcontrol.launch_dependents;");

    __shared__ float xs[BB][KCV];
    __shared__ unsigned s_base;
    const int tid = threadIdx.x;
    const int bid = blockIdx.x;

    if (tid == 0)
        s_base = (atomicAdd(&g_bar, 0u) / (3u * GA)) * (3u * GA);
    __syncthreads();
    const unsigned base = s_base;

    const int oc   = bid & 7;            // 8 o-chunks of 64 float4 columns
    const int kc   = bid >> 3;           // 32 k-chunks
    const int lane = tid & 63;
    const int b    = tid >> 6;
    const int o4   = oc * 64 + lane;

    // ---- Phase 1: PM[kc][b][o] = sum_{i in chunk} zH[b,i] * W_mem[i,o] ----
    if (tid < BB * KCM) {                // 64 staged values
        int bb = tid >> 4, j = tid & 15;
        xs[bb][j] = zH[bb * D_H + kc * KCM + j];
    }
    __syncthreads();
    {
        const float4* W4 = reinterpret_cast<const float4*>(Wm)
                         + (size_t)(kc * KCM) * O4 + o4;
        float4 a = {0.f, 0.f, 0.f, 0.f};
        #pragma unroll
        for (int j = 0; j < KCM; ++j) {
            float4 w = W4[(size_t)j * O4];
            float  x = xs[b][j];
            a.x += x * w.x; a.y += x * w.y; a.z += x * w.z; a.w += x * w.w;
        }
        reinterpret_cast<float4*>(g_PM)[((size_t)kc * BB + b) * O4 + o4] = a;
    }
    gemv_bar(base, 1);

    // ---- Phase 2: PV[kc][b][o] = sum_{i in chunk} mem[b,i] * W_v[i,o] ----
    {   // fold the 32 PM partials while staging (L2-hot)
        int bb = tid >> 6, j = tid & 63;
        int col = kc * KCV + j;
        float s = 0.f;
        #pragma unroll
        for (int p = 0; p < NKM; ++p)
            s += g_PM[((size_t)p * BB + bb) * D_MODEL + col];
        xs[bb][j] = s;
    }
    __syncthreads();
    {
        const float4* W4 = reinterpret_cast<const float4*>(Wv)
                         + (size_t)(kc * KCV) * O4 + o4;
        float4 a = {0.f, 0.f, 0.f, 0.f};
        #pragma unroll 16
        for (int j = 0; j < KCV; ++j) {
            float4 w = W4[(size_t)j * O4];
            float  x = xs[b][j];
            a.x += x * w.x; a.y += x * w.y; a.z += x * w.z; a.w += x * w.w;
        }
        reinterpret_cast<float4*>(g_PV)[((size_t)kc * BB + b) * O4 + o4] = a;
    }
    gemv_bar(base, 2);

    // ---- Phase 3: POV[kc][b][o] = sum_{i in chunk} V[b,i] * W_o[i,o] ----
    {
        int bb = tid >> 6, j = tid & 63;
        int col = kc * KCV + j;
        float s = 0.f;
        #pragma unroll
        for (int p = 0; p < NKV; ++p)
            s += g_PV[((size_t)p * BB + bb) * D_MODEL + col];
        xs[bb][j] = s;
    }
    __syncthreads();
    {
        const float4* W4 = reinterpret_cast<const float4*>(Wo)
                         + (size_t)(kc * KCV) * O4 + o4;
        float4 a = {0.f, 0.f, 0.f, 0.f};
        #pragma unroll 16
        for (int j = 0; j < KCV; ++j) {
            float4 w = W4[(size_t)j * O4];
            float  x = xs[b][j];
            a.x += x * w.x; a.y += x * w.y; a.z += x * w.z; a.w += x * w.w;
        }
        reinterpret_cast<float4*>(g_POV)[((size_t)kc * BB + b) * O4 + o4] = a;
    }
    gemv_bar(base, 3);

    // ---- Phase 4 (blocks 0..31): g_OV = sigmoid(gate) * sum_p POV[p] ----
    if (bid < 32) {
        int e  = bid * NT + tid;
        int bb = e >> 11;
        int o  = e & (D_MODEL - 1);
        float s = 0.f;
        #pragma unroll
        for (int p = 0; p < NKV; ++p)
            s += g_POV[((size_t)p * BB + bb) * D_MODEL + o];
        const float gv = *gate;
        g_OV[e] = s * (1.f / (1.f + expf(-gv)));
    }
    // Kernel completion releases the PDL dependents' griddepcontrol.wait.
}

// ---------------------------------------------------------------------------
// Kernel B: stream  out[b,t,:] = lh[b,t,:] + g_OV[b,:]
// PDL: prefetch own L2 region while kernel A still runs, then wait, then add.
// ---------------------------------------------------------------------------
__global__ void __launch_bounds__(NT, 4) k_stream(
    const float* __restrict__ lh, float* __restrict__ out)
{
    const int tid = threadIdx.x;
    const int bid = blockIdx.x;

    const int start = bid * RPB_LO + (bid < RPB_REM ? bid : RPB_REM);
    const int count = RPB_LO + (bid < RPB_REM ? 1 : 0);

    // Prefetch first 12 rows of this block's region into L2 (independent of A).
    {
        const float* pf = lh + (size_t)start * D_MODEL;
        #pragma unroll
        for (int i = 0; i < PF_LINES; ++i)
            asm volatile("prefetch.global.L2 [%0];"
                         :: "l"(pf + ((size_t)i * NT + tid) * 32));
    }

    // Wait for kernel A completion (g_OV visible). No-op if PDL not active
    // (then stream-order serialization already guarantees A finished).
    asm volatile("griddepcontrol.wait;");

    const float4* OV4 = reinterpret_cast<const float4*>(g_OV);
    const float4* LH  = reinterpret_cast<const float4*>(lh);
    float4*       O   = reinterpret_cast<float4*>(out);

    size_t idx = (size_t)start * O4 + tid;
    #pragma unroll 4
    for (int r = 0; r < count; ++r) {
        const int cb  = (start + r) >> 12;         // batch of this row
        const float4 ov0 = OV4[cb * O4 + tid];     // L1-hot after first touch
        const float4 ov1 = OV4[cb * O4 + tid + NT];

        float4 x0 = LH[idx];
        float4 x1 = LH[idx + NT];
        x0.x += ov0.x; x0.y += ov0.y; x0.z += ov0.z; x0.w += ov0.w;
        x1.x += ov1.x; x1.y += ov1.y; x1.z += ov1.z; x1.w += ov1.w;
        O[idx]      = x0;
        O[idx + NT] = x1;
        idx += O4;
    }
}

// ---------------------------------------------------------------------------
// Input order: 0 last_hidden, 1 zH, 2 W_mem, 3 W_q, 4 W_k, 5 W_v, 6 W_o, 7 gate
// ---------------------------------------------------------------------------
extern "C" void kernel_launch(void* const* d_in, const int* in_sizes, int n_in,
                              void* d_out, int out_size) {
    const float* lh   = (const float*)d_in[0];
    const float* zH   = (const float*)d_in[1];
    const float* Wm   = (const float*)d_in[2];
    const float* Wv   = (const float*)d_in[5];
    const float* Wo   = (const float*)d_in[6];
    const float* gate = (const float*)d_in[7];
    float* out = (float*)d_out;

    k_gemv<<<GA, NT>>>(zH, Wm, Wv, Wo, gate);

    // Stream kernel with programmatic dependent launch (overlaps A's tail).
    cudaLaunchConfig_t cfg = {};
    cfg.gridDim  = dim3(GB, 1, 1);
    cfg.blockDim = dim3(NT, 1, 1);
    cfg.dynamicSmemBytes = 0;
    cfg.stream = (cudaStream_t)0;   // legacy default stream (matches <<< >>>)
    cudaLaunchAttribute attr[1];
    attr[0].id = cudaLaunchAttributeProgrammaticStreamSerialization;
    attr[0].val.programmaticStreamSerializationAllowed = 1;
    cfg.attrs = attr;
    cfg.numAttrs = 1;

    cudaError_t e = cudaLaunchKernelEx(&cfg, k_stream, lh, out);
    if (e != cudaSuccess) {
        // Fallback: plain stream-ordered launch (correct, just no overlap).
        k_stream<<<GB, NT>>>(lh, out);
    }
}